// round 6
// baseline (speedup 1.0000x reference)
#include <cuda_runtime.h>

// Shapes (fixed for this problem): n=1024 tokens, 2L=512, H=512, H2=256.
#define NTOK 1024
#define KIN  512     // 2L
#define HH   512     // H
#define H2D  256     // H2
#define SCALE_2LOG2E 2.885390081777927f   // 2*log2(e)

// Scratch (device globals; no allocations allowed)
__device__ float g_ah[NTOK * HH];
__device__ float g_am[NTOK * HH];
__device__ float g_P[NTOK * H2D];   // c * A            (head side)
__device__ float g_Q[NTOK * H2D];   // c * (B + h2bias) (mod side)
__device__ float g_C;               // sum(w) + outBias

// tanh(x) = 1 - 2/(exp(2x)+1), exact for +/-inf tails, ~1e-6 rel error.
__device__ __forceinline__ float fast_tanh(float x) {
    float e;
    asm("ex2.approx.f32 %0, %1;" : "=f"(e) : "f"(x * SCALE_2LOG2E));
    float r;
    asm("rcp.approx.f32 %0, %1;" : "=f"(r) : "f"(e + 1.0f));
    return 1.0f - 2.0f * r;
}

// ---------------------------------------------------------------------------
// Kernel 1: [ah | am] = tanh( x @ [W_foh | W_fom] + catBias )
// x[m,k] = (k<256) ? lstms0[m,k] : lstms1[m,k-256]
// Combined N = 1024 (first 512 cols -> g_ah with W_foh, next 512 -> g_am).
// Tiling: 64x64 block tile, BK=16, 256 threads, 4x4 micro-tile.
// ---------------------------------------------------------------------------
__global__ __launch_bounds__(256)
void gemm1_tanh(const float* __restrict__ l0, const float* __restrict__ l1,
                const float* __restrict__ Wfoh, const float* __restrict__ Wfom,
                const float* __restrict__ catBias) {
    __shared__ __align__(16) float As[16][68];   // A transposed: As[k][m]
    __shared__ __align__(16) float Bs[16][68];   // Bs[k][n]

    const int tid = threadIdx.x;
    const int n0 = blockIdx.x * 64;      // combined N index
    const int m0 = blockIdx.y * 64;

    const bool head = (n0 < 512);
    const float* __restrict__ W = head ? Wfoh : Wfom;
    const int   wcol = head ? n0 : (n0 - 512);
    float* __restrict__ out = head ? g_ah : g_am;

    const int tx = tid & 15;             // n micro dir
    const int ty = tid >> 4;             // m micro dir

    // A-load indexing: 64 rows x 16 k, one float4 per thread
    const int lm  = tid >> 2;            // 0..63
    const int lk4 = (tid & 3) * 4;       // 0,4,8,12
    // B-load indexing: 16 k x 64 n, one float4 per thread
    const int lk  = tid >> 4;            // 0..15
    const int ln  = (tid & 15) * 4;      // 0..60

    float acc[4][4] = {};

    for (int k0 = 0; k0 < KIN; k0 += 16) {
        const float* __restrict__ xsrc =
            (k0 < 256) ? (l0 + (size_t)(m0 + lm) * 256 + (k0 + lk4))
                       : (l1 + (size_t)(m0 + lm) * 256 + (k0 - 256 + lk4));
        float4 av = *(const float4*)xsrc;
        As[lk4 + 0][lm] = av.x;
        As[lk4 + 1][lm] = av.y;
        As[lk4 + 2][lm] = av.z;
        As[lk4 + 3][lm] = av.w;

        float4 bv = *(const float4*)(W + (size_t)(k0 + lk) * HH + wcol + ln);
        *(float4*)&Bs[lk][ln] = bv;

        __syncthreads();
#pragma unroll
        for (int kk = 0; kk < 16; kk++) {
            float4 a4 = *(const float4*)&As[kk][ty * 4];
            float4 b4 = *(const float4*)&Bs[kk][tx * 4];
            float aa[4] = {a4.x, a4.y, a4.z, a4.w};
            float bb[4] = {b4.x, b4.y, b4.z, b4.w};
#pragma unroll
            for (int i = 0; i < 4; i++)
#pragma unroll
                for (int j = 0; j < 4; j++)
                    acc[i][j] = fmaf(aa[i], bb[j], acc[i][j]);
        }
        __syncthreads();
    }

#pragma unroll
    for (int j = 0; j < 4; j++) {
        const float bias = catBias[n0 + tx * 4 + j];   // combined index works for both halves
#pragma unroll
        for (int i = 0; i < 4; i++) {
            float v = fast_tanh(acc[i][j] + bias);
            out[(size_t)(m0 + ty * 4 + i) * HH + wcol + tx * 4 + j] = v;
        }
    }
}

// ---------------------------------------------------------------------------
// Kernel 2: P = c * (ah @ hid2Layer[0:512])
//           Q = c * (am @ hid2Layer[512:1024] + hid2Bias)
// Combined N = 512 (first 256 -> P, next 256 -> Q). Same tiling as kernel 1.
// ---------------------------------------------------------------------------
__global__ __launch_bounds__(256)
void gemm2_pq(const float* __restrict__ h2L, const float* __restrict__ h2B) {
    __shared__ __align__(16) float As[16][68];
    __shared__ __align__(16) float Bs[16][68];

    const int tid = threadIdx.x;
    const int n0 = blockIdx.x * 64;      // combined N index (0..511)
    const int m0 = blockIdx.y * 64;

    const bool isP = (n0 < 256);
    const float* __restrict__ Asrc = isP ? g_ah : g_am;
    const int   wrow = isP ? 0 : 512;
    const int   col0 = isP ? n0 : (n0 - 256);
    float* __restrict__ out = isP ? g_P : g_Q;

    const int tx = tid & 15;
    const int ty = tid >> 4;
    const int lm  = tid >> 2;
    const int lk4 = (tid & 3) * 4;
    const int lk  = tid >> 4;
    const int ln  = (tid & 15) * 4;

    float acc[4][4] = {};

    for (int k0 = 0; k0 < HH; k0 += 16) {
        float4 av = *(const float4*)(Asrc + (size_t)(m0 + lm) * HH + k0 + lk4);
        As[lk4 + 0][lm] = av.x;
        As[lk4 + 1][lm] = av.y;
        As[lk4 + 2][lm] = av.z;
        As[lk4 + 3][lm] = av.w;

        float4 bv = *(const float4*)(h2L + (size_t)(wrow + k0 + lk) * H2D + col0 + ln);
        *(float4*)&Bs[lk][ln] = bv;

        __syncthreads();
#pragma unroll
        for (int kk = 0; kk < 16; kk++) {
            float4 a4 = *(const float4*)&As[kk][ty * 4];
            float4 b4 = *(const float4*)&Bs[kk][tx * 4];
            float aa[4] = {a4.x, a4.y, a4.z, a4.w};
            float bb[4] = {b4.x, b4.y, b4.z, b4.w};
#pragma unroll
            for (int i = 0; i < 4; i++)
#pragma unroll
                for (int j = 0; j < 4; j++)
                    acc[i][j] = fmaf(aa[i], bb[j], acc[i][j]);
        }
        __syncthreads();
    }

#pragma unroll
    for (int j = 0; j < 4; j++) {
        const float bias = isP ? 0.0f : h2B[col0 + tx * 4 + j];
#pragma unroll
        for (int i = 0; i < 4; i++) {
            float v = (acc[i][j] + bias) * SCALE_2LOG2E;
            out[(size_t)(m0 + ty * 4 + i) * H2D + col0 + tx * 4 + j] = v;
        }
    }
}

// ---------------------------------------------------------------------------
// Kernel 3: g_C = sum(outLayer) + outBias
// ---------------------------------------------------------------------------
__global__ void sumw_kernel(const float* __restrict__ outL,
                            const float* __restrict__ outB) {
    __shared__ float s[256];
    s[threadIdx.x] = outL[threadIdx.x];
    __syncthreads();
    for (int o = 128; o > 0; o >>= 1) {
        if (threadIdx.x < o) s[threadIdx.x] += s[threadIdx.x + o];
        __syncthreads();
    }
    if (threadIdx.x == 0) g_C = s[0] + outB[0];
}

// ---------------------------------------------------------------------------
// Kernel 4: pairwise scores.
// scores[i,j] = C + sum_h (-2*w_h) * rcp(ex2(P[i,h]+Q[j,h]) + 1)
// Block computes a 16x16 (i,j) tile; P/Q rows staged in smem; float4 inner loop.
// MUFU-bound: 2 MUFU per element.
// ---------------------------------------------------------------------------
__device__ __forceinline__ float pterm(float x, float w, float acc) {
    float e;
    asm("ex2.approx.f32 %0, %1;" : "=f"(e) : "f"(x));
    float r;
    asm("rcp.approx.f32 %0, %1;" : "=f"(r) : "f"(e + 1.0f));
    return fmaf(w, r, acc);
}

__global__ __launch_bounds__(256)
void pairwise_kernel(const float* __restrict__ outL, float* __restrict__ out) {
    __shared__ __align__(16) float Ps[16][260];
    __shared__ __align__(16) float Qs[16][260];
    __shared__ __align__(16) float ws[256];

    const int tid = threadIdx.x;
    const int j0 = blockIdx.x * 16;
    const int i0 = blockIdx.y * 16;

    // Stage 16x256 P rows and 16x256 Q rows (float4, fully coalesced)
#pragma unroll
    for (int r = 0; r < 4; r++) {
        int lin = tid + r * 256;          // 0..1023
        int row = lin >> 6;               // 0..15
        int c   = (lin & 63) * 4;         // float col 0..252 step 4
        *(float4*)&Ps[row][c] = *(const float4*)&g_P[(size_t)(i0 + row) * H2D + c];
        *(float4*)&Qs[row][c] = *(const float4*)&g_Q[(size_t)(j0 + row) * H2D + c];
    }
    ws[tid] = -2.0f * outL[tid];
    __syncthreads();

    const int tj = tid & 15;   // j fast -> coalesced stores
    const int ti = tid >> 4;

    const float* __restrict__ prow = &Ps[ti][0];
    const float* __restrict__ qrow = &Qs[tj][0];

    float acc0 = 0.f, acc1 = 0.f, acc2 = 0.f, acc3 = 0.f;
#pragma unroll 16
    for (int h4 = 0; h4 < 64; h4++) {
        float4 p = *(const float4*)(prow + h4 * 4);
        float4 q = *(const float4*)(qrow + h4 * 4);
        float4 w = *(const float4*)(ws + h4 * 4);
        acc0 = pterm(p.x + q.x, w.x, acc0);
        acc1 = pterm(p.y + q.y, w.y, acc1);
        acc2 = pterm(p.z + q.z, w.z, acc2);
        acc3 = pterm(p.w + q.w, w.w, acc3);
    }
    float score = g_C + ((acc0 + acc1) + (acc2 + acc3));
    out[(size_t)(i0 + ti) * NTOK + (j0 + tj)] = score;
}

// ---------------------------------------------------------------------------
extern "C" void kernel_launch(void* const* d_in, const int* in_sizes, int n_in,
                              void* d_out, int out_size) {
    const float* l0   = (const float*)d_in[0];   // lstms0 [1024,256]
    const float* l1   = (const float*)d_in[1];   // lstms1 [1024,256]
    const float* Wfoh = (const float*)d_in[2];   // [512,512]
    const float* Wfom = (const float*)d_in[3];   // [512,512]
    const float* catB = (const float*)d_in[4];   // [1,1024]
    const float* h2L  = (const float*)d_in[5];   // [1024,256]
    const float* h2B  = (const float*)d_in[6];   // [1,256]
    const float* outL = (const float*)d_in[7];   // [256,1]
    const float* outB = (const float*)d_in[8];   // [1,1]
    float* out = (float*)d_out;                  // [1024,1024]

    gemm1_tanh<<<dim3(16, 16), 256>>>(l0, l1, Wfoh, Wfom, catB);
    gemm2_pq<<<dim3(8, 16), 256>>>(h2L, h2B);
    sumw_kernel<<<1, 256>>>(outL, outB);
    pairwise_kernel<<<dim3(64, 64), 256>>>(outL, out);
}

// round 7
// speedup vs baseline: 1.1602x; 1.1602x over previous
#include <cuda_runtime.h>

// Shapes (fixed): n=1024 tokens, 2L=512, H=512, H2=256.
#define NTOK 1024
#define KIN  512
#define HH   512
#define H2D  256
#define SCALE_2LOG2E 2.885390081777927f   // 2*log2(e)

// Scratch (device globals; no allocations allowed)
__device__ float g_ah[NTOK * HH];
__device__ float g_am[NTOK * HH];
__device__ float g_Ep[NTOK * H2D];  // ex2(c*A)             (head side)
__device__ float g_Eq[NTOK * H2D];  // ex2(c*(B + h2bias))  (mod side)
__device__ float g_C;               // sum(w) + outBias

// tanh(x) = 1 - 2/(exp(2x)+1); exact tails, ~1e-6 rel error.
__device__ __forceinline__ float fast_tanh(float x) {
    float e;
    asm("ex2.approx.f32 %0, %1;" : "=f"(e) : "f"(x * SCALE_2LOG2E));
    float r;
    asm("rcp.approx.f32 %0, %1;" : "=f"(r) : "f"(e + 1.0f));
    return 1.0f - 2.0f * r;
}

__device__ __forceinline__ float fast_ex2(float x) {
    float e;
    asm("ex2.approx.f32 %0, %1;" : "=f"(e) : "f"(x));
    return e;
}

// ---------------------------------------------------------------------------
// Kernel 1: [ah | am] = tanh( x @ [W_foh | W_fom] + catBias )
// 128x64 block tile, BK=16, 256 threads, 8x4 micro-tile. Grid (16,8) = 128
// blocks -> single wave on 148 SMs.
// ---------------------------------------------------------------------------
__global__ __launch_bounds__(256)
void gemm1_tanh(const float* __restrict__ l0, const float* __restrict__ l1,
                const float* __restrict__ Wfoh, const float* __restrict__ Wfom,
                const float* __restrict__ catBias) {
    __shared__ __align__(16) float As[16][132];   // As[k][m], m tile = 128
    __shared__ __align__(16) float Bs[16][68];    // Bs[k][n], n tile = 64

    const int tid = threadIdx.x;
    const int n0 = blockIdx.x * 64;       // combined N index (0..1023)
    const int m0 = blockIdx.y * 128;

    const bool head = (n0 < 512);
    const float* __restrict__ W = head ? Wfoh : Wfom;
    const int   wcol = head ? n0 : (n0 - 512);
    float* __restrict__ out = head ? g_ah : g_am;

    const int tx = tid & 15;              // n micro dir (4 cols)
    const int ty = tid >> 4;              // m micro dir (8 rows)

    // B-load indexing: 16 k x 64 n, one float4 per thread
    const int lk = tid >> 4;
    const int ln = (tid & 15) * 4;

    float acc[8][4] = {};

    for (int k0 = 0; k0 < KIN; k0 += 16) {
        // A tile: 128 x 16 = 512 float4, 2 per thread (transposed into smem)
#pragma unroll
        for (int p = 0; p < 2; p++) {
            int lin = tid + p * 256;
            int lm  = lin >> 2;            // 0..127
            int lk4 = (lin & 3) * 4;
            const float* __restrict__ xsrc =
                (k0 < 256) ? (l0 + (size_t)(m0 + lm) * 256 + (k0 + lk4))
                           : (l1 + (size_t)(m0 + lm) * 256 + (k0 - 256 + lk4));
            float4 av = *(const float4*)xsrc;
            As[lk4 + 0][lm] = av.x;
            As[lk4 + 1][lm] = av.y;
            As[lk4 + 2][lm] = av.z;
            As[lk4 + 3][lm] = av.w;
        }
        float4 bv = *(const float4*)(W + (size_t)(k0 + lk) * HH + wcol + ln);
        *(float4*)&Bs[lk][ln] = bv;

        __syncthreads();
#pragma unroll
        for (int kk = 0; kk < 16; kk++) {
            float4 a0 = *(const float4*)&As[kk][ty * 8];
            float4 a1 = *(const float4*)&As[kk][ty * 8 + 4];
            float4 b4 = *(const float4*)&Bs[kk][tx * 4];
            float aa[8] = {a0.x, a0.y, a0.z, a0.w, a1.x, a1.y, a1.z, a1.w};
            float bb[4] = {b4.x, b4.y, b4.z, b4.w};
#pragma unroll
            for (int i = 0; i < 8; i++)
#pragma unroll
                for (int j = 0; j < 4; j++)
                    acc[i][j] = fmaf(aa[i], bb[j], acc[i][j]);
        }
        __syncthreads();
    }

    const float4 bias4 = *(const float4*)&catBias[n0 + tx * 4];
#pragma unroll
    for (int i = 0; i < 8; i++) {
        float4 v;
        v.x = fast_tanh(acc[i][0] + bias4.x);
        v.y = fast_tanh(acc[i][1] + bias4.y);
        v.z = fast_tanh(acc[i][2] + bias4.z);
        v.w = fast_tanh(acc[i][3] + bias4.w);
        *(float4*)&out[(size_t)(m0 + ty * 8 + i) * HH + wcol + tx * 4] = v;
    }
}

// ---------------------------------------------------------------------------
// Kernel 2: Ep = ex2( c * (ah @ hid2Layer[0:512]) )
//           Eq = ex2( c * (am @ hid2Layer[512:1024] + hid2Bias) )
// 64x64 tile, BK=16, 256 threads, 4x4 micro. Grid (8,16) = 128 blocks.
// ---------------------------------------------------------------------------
__global__ __launch_bounds__(256)
void gemm2_exp(const float* __restrict__ h2L, const float* __restrict__ h2B) {
    __shared__ __align__(16) float As[16][68];
    __shared__ __align__(16) float Bs[16][68];

    const int tid = threadIdx.x;
    const int n0 = blockIdx.x * 64;       // combined N (0..511)
    const int m0 = blockIdx.y * 64;

    const bool isP = (n0 < 256);
    const float* __restrict__ Asrc = isP ? g_ah : g_am;
    const int   wrow = isP ? 0 : 512;
    const int   col0 = isP ? n0 : (n0 - 256);
    float* __restrict__ out = isP ? g_Ep : g_Eq;

    const int tx = tid & 15;
    const int ty = tid >> 4;
    const int lm  = tid >> 2;
    const int lk4 = (tid & 3) * 4;
    const int lk  = tid >> 4;
    const int ln  = (tid & 15) * 4;

    float acc[4][4] = {};

    for (int k0 = 0; k0 < HH; k0 += 16) {
        float4 av = *(const float4*)(Asrc + (size_t)(m0 + lm) * HH + k0 + lk4);
        As[lk4 + 0][lm] = av.x;
        As[lk4 + 1][lm] = av.y;
        As[lk4 + 2][lm] = av.z;
        As[lk4 + 3][lm] = av.w;

        float4 bv = *(const float4*)(h2L + (size_t)(wrow + k0 + lk) * H2D + col0 + ln);
        *(float4*)&Bs[lk][ln] = bv;

        __syncthreads();
#pragma unroll
        for (int kk = 0; kk < 16; kk++) {
            float4 a4 = *(const float4*)&As[kk][ty * 4];
            float4 b4 = *(const float4*)&Bs[kk][tx * 4];
            float aa[4] = {a4.x, a4.y, a4.z, a4.w};
            float bb[4] = {b4.x, b4.y, b4.z, b4.w};
#pragma unroll
            for (int i = 0; i < 4; i++)
#pragma unroll
                for (int j = 0; j < 4; j++)
                    acc[i][j] = fmaf(aa[i], bb[j], acc[i][j]);
        }
        __syncthreads();
    }

#pragma unroll
    for (int j = 0; j < 4; j++) {
        const float bias = isP ? 0.0f : h2B[col0 + tx * 4 + j];
#pragma unroll
        for (int i = 0; i < 4; i++) {
            float v = fast_ex2((acc[i][j] + bias) * SCALE_2LOG2E);
            out[(size_t)(m0 + ty * 4 + i) * H2D + col0 + tx * 4 + j] = v;
        }
    }
}

// ---------------------------------------------------------------------------
// Kernel 3: g_C = sum(outLayer) + outBias
// ---------------------------------------------------------------------------
__global__ void sumw_kernel(const float* __restrict__ outL,
                            const float* __restrict__ outB) {
    __shared__ float s[256];
    s[threadIdx.x] = outL[threadIdx.x];
    __syncthreads();
    for (int o = 128; o > 0; o >>= 1) {
        if (threadIdx.x < o) s[threadIdx.x] += s[threadIdx.x + o];
        __syncthreads();
    }
    if (threadIdx.x == 0) g_C = s[0] + outB[0];
}

// ---------------------------------------------------------------------------
// Kernel 4: pairwise scores, exp-factorized (1 MUFU + 2 FMA per element):
//   scores[i,j] = C + sum_h (-2*w_h) * rcp( Ep[i,h]*Eq[j,h] + 1 )
// Block: 32x32 (i,j) tile, 256 threads, 2x2 micro-tile per thread.
// h processed in two 128-chunks so smem stays at ~34 KB (static limit).
// ---------------------------------------------------------------------------
__device__ __forceinline__ float pterm(float ep, float eq, float w, float acc) {
    float t = fmaf(ep, eq, 1.0f);
    float r;
    asm("rcp.approx.f32 %0, %1;" : "=f"(r) : "f"(t));
    return fmaf(w, r, acc);
}

__global__ __launch_bounds__(256)
void pairwise_kernel(const float* __restrict__ outL, float* __restrict__ out) {
    __shared__ __align__(16) float Eps[32][132];
    __shared__ __align__(16) float Eqs[32][132];
    __shared__ __align__(16) float ws[256];

    const int tid = threadIdx.x;
    const int j0 = blockIdx.x * 32;
    const int i0 = blockIdx.y * 32;

    ws[tid] = -2.0f * outL[tid];

    const int tj = tid & 15;     // j fast -> coalesced stores
    const int ti = tid >> 4;

    float acc00 = 0.f, acc01 = 0.f, acc10 = 0.f, acc11 = 0.f;

    for (int ph = 0; ph < 2; ph++) {
        __syncthreads();   // first pass: ws visible; later: prior reads done
        // Stage 32 rows x 128 floats of Ep and Eq (1024 float4 each)
#pragma unroll
        for (int p = 0; p < 4; p++) {
            int lin = tid + p * 256;
            int row = lin >> 5;           // 0..31
            int c   = (lin & 31) * 4;     // 0..124 step 4
            *(float4*)&Eps[row][c] =
                *(const float4*)&g_Ep[(size_t)(i0 + row) * H2D + ph * 128 + c];
            *(float4*)&Eqs[row][c] =
                *(const float4*)&g_Eq[(size_t)(j0 + row) * H2D + ph * 128 + c];
        }
        __syncthreads();

        const float* __restrict__ p0 = &Eps[2 * ti][0];
        const float* __restrict__ p1 = &Eps[2 * ti + 1][0];
        const float* __restrict__ q0 = &Eqs[2 * tj][0];
        const float* __restrict__ q1 = &Eqs[2 * tj + 1][0];
        const float* __restrict__ pw = &ws[ph * 128];

#pragma unroll 8
        for (int h4 = 0; h4 < 32; h4++) {
            float4 a0 = *(const float4*)(p0 + h4 * 4);
            float4 a1 = *(const float4*)(p1 + h4 * 4);
            float4 b0 = *(const float4*)(q0 + h4 * 4);
            float4 b1 = *(const float4*)(q1 + h4 * 4);
            float4 w4 = *(const float4*)(pw + h4 * 4);

            acc00 = pterm(a0.x, b0.x, w4.x, acc00);
            acc01 = pterm(a0.x, b1.x, w4.x, acc01);
            acc10 = pterm(a1.x, b0.x, w4.x, acc10);
            acc11 = pterm(a1.x, b1.x, w4.x, acc11);

            acc00 = pterm(a0.y, b0.y, w4.y, acc00);
            acc01 = pterm(a0.y, b1.y, w4.y, acc01);
            acc10 = pterm(a1.y, b0.y, w4.y, acc10);
            acc11 = pterm(a1.y, b1.y, w4.y, acc11);

            acc00 = pterm(a0.z, b0.z, w4.z, acc00);
            acc01 = pterm(a0.z, b1.z, w4.z, acc01);
            acc10 = pterm(a1.z, b0.z, w4.z, acc10);
            acc11 = pterm(a1.z, b1.z, w4.z, acc11);

            acc00 = pterm(a0.w, b0.w, w4.w, acc00);
            acc01 = pterm(a0.w, b1.w, w4.w, acc01);
            acc10 = pterm(a1.w, b0.w, w4.w, acc10);
            acc11 = pterm(a1.w, b1.w, w4.w, acc11);
        }
    }

    const float C = g_C;
    const int i = i0 + 2 * ti;
    const int j = j0 + 2 * tj;
    float2 r0 = make_float2(C + acc00, C + acc01);
    float2 r1 = make_float2(C + acc10, C + acc11);
    *(float2*)&out[(size_t)i * NTOK + j]       = r0;
    *(float2*)&out[(size_t)(i + 1) * NTOK + j] = r1;
}

// ---------------------------------------------------------------------------
extern "C" void kernel_launch(void* const* d_in, const int* in_sizes, int n_in,
                              void* d_out, int out_size) {
    const float* l0   = (const float*)d_in[0];   // lstms0 [1024,256]
    const float* l1   = (const float*)d_in[1];   // lstms1 [1024,256]
    const float* Wfoh = (const float*)d_in[2];   // [512,512]
    const float* Wfom = (const float*)d_in[3];   // [512,512]
    const float* catB = (const float*)d_in[4];   // [1,1024]
    const float* h2L  = (const float*)d_in[5];   // [1024,256]
    const float* h2B  = (const float*)d_in[6];   // [1,256]
    const float* outL = (const float*)d_in[7];   // [256,1]
    const float* outB = (const float*)d_in[8];   // [1,1]
    float* out = (float*)d_out;                  // [1024,1024]

    gemm1_tanh<<<dim3(16, 8), 256>>>(l0, l1, Wfoh, Wfom, catB);
    gemm2_exp<<<dim3(8, 16), 256>>>(h2L, h2B);
    sumw_kernel<<<1, 256>>>(outL, outB);
    pairwise_kernel<<<dim3(32, 32), 256>>>(outL, out);
}